// round 1
// baseline (speedup 1.0000x reference)
#include <cuda_runtime.h>
#include <math.h>

#define Bb   8
#define Cc   32
#define Ll   90000
#define DOWNL 22500
#define FLATN 1440000

#define TILE_T 256
#define SH_STR 292     // 288 cols (256 + 32 halo) padded to mult-of-4
#define SO_STR 260     // 256 cols padded

// ---- scratch (device globals; no allocation allowed) ----
__device__ float g_hA[Bb*Cc*Ll];     // 92 MB
__device__ float g_hB[Bb*Cc*Ll];     // 92 MB
__device__ float g_skip[Bb*Cc*Ll];   // 92 MB
__device__ float g_y[Bb*FLATN];      // 46 MB
__device__ float g_o[Bb*64];

__device__ __forceinline__ float fsig(float x)  { return 1.0f / (1.0f + __expf(-x)); }
__device__ __forceinline__ float ftanh(float x) { return 2.0f * fsig(2.0f * x) - 1.0f; }

// ---------------- conv0: x[B,1,L] -> h0[B,32,L] (K=3, causal) ----------------
__global__ void conv0_kernel(const float* __restrict__ x,
                             const float* __restrict__ w0,
                             const float* __restrict__ b0)
{
    int t  = blockIdx.x * blockDim.x + threadIdx.x;
    int bc = blockIdx.y;           // b*32 + c
    if (t >= Ll) return;
    int b = bc >> 5, c = bc & 31;
    const float* xb = x + b * Ll;
    float wk0 = w0[c*3+0], wk1 = w0[c*3+1], wk2 = w0[c*3+2];
    float v = wk2 * xb[t] + b0[c];
    if (t >= 1) v += wk1 * xb[t-1];
    if (t >= 2) v += wk0 * xb[t-2];
    g_hA[(b*Cc + c)*Ll + t] = v;
}

// ---------------- one WaveNet block ----------------
// h_out = h_in + r ; skip (+)= s ; ping selects buffers
template<int DIL, bool FIRST>
__global__ void __launch_bounds__(256, 2)
wavenet_block(int ping,
              const float* __restrict__ Wf, const float* __restrict__ bf,
              const float* __restrict__ Wg, const float* __restrict__ bg,
              const float* __restrict__ Ws, const float* __restrict__ bs,
              const float* __restrict__ Wr, const float* __restrict__ br)
{
    extern __shared__ float smem[];
    float4* sWfg = (float4*)smem;                    // [32c][32k] {wf0,wf1,wg0,wg1}
    float2* sWsr = (float2*)(smem + 4096);           // [32c][32k] {ws,wr}
    float*  sH   = smem + 6144;                      // [32][SH_STR]
    float*  sO   = smem + 6144 + 32*SH_STR;          // [32][SO_STR]

    const float* h_in  = ping ? g_hB : g_hA;
    float*       h_out = ping ? g_hA : g_hB;

    const int tid   = threadIdx.x;
    const int b     = blockIdx.y;
    const int tile0 = blockIdx.x * TILE_T;

    // pack weights into shared
    for (int e = tid; e < 1024; e += 256) {
        int o = e >> 5, k = e & 31;
        sWfg[e] = make_float4(Wf[o*64 + k*2 + 0], Wf[o*64 + k*2 + 1],
                              Wg[o*64 + k*2 + 0], Wg[o*64 + k*2 + 1]);
        sWsr[e] = make_float2(Ws[o*32 + k], Wr[o*32 + k]);
    }
    // load h tile with left halo of 32
    const float* hb = h_in + (size_t)b * Cc * Ll;
    for (int e = tid; e < 32*288; e += 256) {
        int k = e / 288, j = e - k*288;
        int gt = tile0 - 32 + j;
        sH[k*SH_STR + j] = (gt >= 0 && gt < Ll) ? hb[k*Ll + gt] : 0.0f;
    }
    __syncthreads();

    const int cp = tid >> 4;          // 0..15
    const int c0 = cp, c1 = cp + 16;
    const int q  = tid & 15;          // 0..15
    const float bf0 = bf[c0], bf1 = bf[c1];
    const float bg0 = bg[c0], bg1 = bg[c1];
    const float bs0 = bs[c0], bs1 = bs[c1];
    const float br0 = br[c0], br1 = br[c1];

    for (int ss = 0; ss < 4; ++ss) {
        const int tl = ss*64 + q*4;   // 0..255 (mult of 4)
        const int bt = 32 + tl;

        float f0[4], f1[4], g0[4], g1[4];
        #pragma unroll
        for (int j = 0; j < 4; ++j) { f0[j]=bf0; f1[j]=bf1; g0[j]=bg0; g1[j]=bg1; }

        #pragma unroll 4
        for (int k = 0; k < 32; ++k) {
            float4 wa = sWfg[c0*32 + k];
            float4 wb = sWfg[c1*32 + k];
            const float* row = sH + k*SH_STR;
            float4 vt = *(const float4*)(row + bt);
            float4 vs;
            if (DIL >= 4) {
                vs = *(const float4*)(row + bt - DIL);
            } else {
                float4 vp = *(const float4*)(row + bt - 4);
                if (DIL == 1) vs = make_float4(vp.w, vt.x, vt.y, vt.z);
                else          vs = make_float4(vp.z, vp.w, vt.x, vt.y);
            }
            float vta[4] = {vt.x, vt.y, vt.z, vt.w};
            float vsa[4] = {vs.x, vs.y, vs.z, vs.w};
            #pragma unroll
            for (int j = 0; j < 4; ++j) {
                f0[j] += wa.x * vsa[j]; f0[j] += wa.y * vta[j];
                g0[j] += wa.z * vsa[j]; g0[j] += wa.w * vta[j];
                f1[j] += wb.x * vsa[j]; f1[j] += wb.y * vta[j];
                g1[j] += wb.z * vsa[j]; g1[j] += wb.w * vta[j];
            }
        }
        float o0[4], o1[4];
        #pragma unroll
        for (int j = 0; j < 4; ++j) {
            o0[j] = ftanh(f0[j]) * fsig(g0[j]);
            o1[j] = ftanh(f1[j]) * fsig(g1[j]);
        }
        *(float4*)(sO + c0*SO_STR + tl) = make_float4(o0[0], o0[1], o0[2], o0[3]);
        *(float4*)(sO + c1*SO_STR + tl) = make_float4(o1[0], o1[1], o1[2], o1[3]);
        __syncthreads();

        float s0[4], s1[4], r0[4], r1[4];
        #pragma unroll
        for (int j = 0; j < 4; ++j) { s0[j]=bs0; s1[j]=bs1; r0[j]=br0; r1[j]=br1; }

        #pragma unroll 4
        for (int k = 0; k < 32; ++k) {
            float2 wsa = sWsr[c0*32 + k];
            float2 wsb = sWsr[c1*32 + k];
            float4 ov = *(const float4*)(sO + k*SO_STR + tl);
            float oa[4] = {ov.x, ov.y, ov.z, ov.w};
            #pragma unroll
            for (int j = 0; j < 4; ++j) {
                s0[j] += wsa.x * oa[j]; r0[j] += wsa.y * oa[j];
                s1[j] += wsb.x * oa[j]; r1[j] += wsb.y * oa[j];
            }
        }

        int t = tile0 + tl;
        if (t < Ll) {
            float4 hv0 = *(const float4*)(sH + c0*SH_STR + bt);
            float4 hv1 = *(const float4*)(sH + c1*SH_STR + bt);
            size_t i0 = (size_t)(b*Cc + c0)*Ll + t;
            size_t i1 = (size_t)(b*Cc + c1)*Ll + t;
            *(float4*)(h_out + i0) = make_float4(hv0.x+r0[0], hv0.y+r0[1], hv0.z+r0[2], hv0.w+r0[3]);
            *(float4*)(h_out + i1) = make_float4(hv1.x+r1[0], hv1.y+r1[1], hv1.z+r1[2], hv1.w+r1[3]);
            float4 sv0 = make_float4(s0[0], s0[1], s0[2], s0[3]);
            float4 sv1 = make_float4(s1[0], s1[1], s1[2], s1[3]);
            if (!FIRST) {
                float4 p0 = *(const float4*)(g_skip + i0);
                float4 p1 = *(const float4*)(g_skip + i1);
                sv0.x += p0.x; sv0.y += p0.y; sv0.z += p0.z; sv0.w += p0.w;
                sv1.x += p1.x; sv1.y += p1.y; sv1.z += p1.z; sv1.w += p1.w;
            }
            *(float4*)(g_skip + i0) = sv0;
            *(float4*)(g_skip + i1) = sv1;
        }
        // no extra sync needed: next ss writes a disjoint sO column range
        __syncthreads();
    }
}

// ---------------- downsample conv: skip[B,32,L] -> y[B,64,22500] (K=4, stride 4) ----
__global__ void __launch_bounds__(256, 2)
downsample_kernel(const float* __restrict__ wd, const float* __restrict__ bd)
{
    extern __shared__ float smem[];
    float4* sWd = (float4*)smem;          // [64o][32c] as float4 over j  (32 KB)
    float*  sSk = smem + 8192;            // [32][256]                   (32 KB)

    int tid = threadIdx.x;
    int b   = blockIdx.y;
    int u0  = blockIdx.x * 64;
    int t0  = u0 * 4;

    const float4* wd4 = (const float4*)wd;
    for (int e = tid; e < 2048; e += 256) sWd[e] = wd4[e];

    const float* skb = g_skip + (size_t)b * Cc * Ll;
    for (int e = tid; e < 32*256; e += 256) {
        int c = e >> 8, j = e & 255;
        int gt = t0 + j;
        sSk[c*256 + j] = (gt < Ll) ? skb[c*Ll + gt] : 0.0f;
    }
    __syncthreads();

    int op = tid >> 3;            // 0..31
    int o0 = op, o1 = op + 32;
    int qq = tid & 7;             // u_loc = i*8 + qq
    float a0[8], a1[8];
    float bd0 = bd[o0], bd1 = bd[o1];
    #pragma unroll
    for (int i = 0; i < 8; ++i) { a0[i]=bd0; a1[i]=bd1; }

    #pragma unroll 4
    for (int c = 0; c < 32; ++c) {
        float4 w0v = sWd[o0*32 + c];
        float4 w1v = sWd[o1*32 + c];
        const float* sr = sSk + c*256;
        #pragma unroll
        for (int i = 0; i < 8; ++i) {
            float4 sv = *(const float4*)(sr + (i*8 + qq)*4);
            a0[i] += w0v.x*sv.x + w0v.y*sv.y + w0v.z*sv.z + w0v.w*sv.w;
            a1[i] += w1v.x*sv.x + w1v.y*sv.y + w1v.z*sv.z + w1v.w*sv.w;
        }
    }
    float* yb = g_y + (size_t)b * FLATN;
    #pragma unroll
    for (int i = 0; i < 8; ++i) {
        int u = u0 + i*8 + qq;
        if (u < DOWNL) {
            yb[o0*DOWNL + u] = a0[i];
            yb[o1*DOWNL + u] = a1[i];
        }
    }
}

// ---------------- FC: o[b,m] = sum_f fcW[m,f] * y[b,f] ----------------
__global__ void zero_o_kernel() {
    int i = threadIdx.x;
    if (i < Bb*64) g_o[i] = 0.0f;
}

#define FC_CHUNK 2000
__global__ void __launch_bounds__(512, 2)
fc_kernel(const float* __restrict__ fcW)
{
    extern __shared__ float smem[];          // sy[8][FC_CHUNK]  (64000 B)
    int tid = threadIdx.x;
    int f0  = blockIdx.x * FC_CHUNK;
    int mg  = blockIdx.y;                    // 0..1

    for (int e = tid; e < 8*FC_CHUNK; e += 512) {
        int b = e / FC_CHUNK, f = e - b*FC_CHUNK;
        smem[b*FC_CHUNK + f] = g_y[(size_t)b*FLATN + f0 + f];
    }
    __syncthreads();

    int w = tid >> 5, lane = tid & 31;
    int m0 = mg*32 + w;                      // warp handles m0 and m0+16
    float acc0[8], acc1[8];
    #pragma unroll
    for (int b = 0; b < 8; ++b) { acc0[b]=0.f; acc1[b]=0.f; }

    const float* W0 = fcW + (size_t)m0      * FLATN + f0;
    const float* W1 = fcW + (size_t)(m0+16) * FLATN + f0;
    for (int f = lane; f < FC_CHUNK; f += 32) {
        float wv0 = __ldg(W0 + f);
        float wv1 = __ldg(W1 + f);
        #pragma unroll
        for (int b = 0; b < 8; ++b) {
            float yv = smem[b*FC_CHUNK + f];
            acc0[b] += wv0 * yv;
            acc1[b] += wv1 * yv;
        }
    }
    #pragma unroll
    for (int off = 16; off; off >>= 1) {
        #pragma unroll
        for (int b = 0; b < 8; ++b) {
            acc0[b] += __shfl_xor_sync(0xFFFFFFFFu, acc0[b], off);
            acc1[b] += __shfl_xor_sync(0xFFFFFFFFu, acc1[b], off);
        }
    }
    if (lane == 0) {
        #pragma unroll
        for (int b = 0; b < 8; ++b) {
            atomicAdd(&g_o[b*64 + m0],      acc0[b]);
            atomicAdd(&g_o[b*64 + m0 + 16], acc1[b]);
        }
    }
}

// ---------------- final: mu/logvar/z ----------------
__global__ void final_kernel(const float* __restrict__ eps,
                             const float* __restrict__ fcb,
                             float* __restrict__ out)
{
    int i = threadIdx.x;               // 0..255
    int b = i >> 5, l = i & 31;
    float mu = g_o[b*64 + l]      + fcb[l];
    float lv = g_o[b*64 + 32 + l] + fcb[32 + l];
    float z  = mu + eps[b*32 + l] * expf(0.5f * lv);
    out[i]       = mu;
    out[256 + i] = lv;
    out[512 + i] = z;
}

// ---------------- launch ----------------
extern "C" void kernel_launch(void* const* d_in, const int* in_sizes, int n_in,
                              void* d_out, int out_size)
{
    (void)in_sizes; (void)n_in; (void)out_size;
    const float* x   = (const float*)d_in[0];
    const float* eps = (const float*)d_in[1];
    const float* w0  = (const float*)d_in[2];
    const float* b0  = (const float*)d_in[3];
    const float* Wf  = (const float*)d_in[4];
    const float* bf  = (const float*)d_in[5];
    const float* Wg  = (const float*)d_in[6];
    const float* bg  = (const float*)d_in[7];
    const float* Ws  = (const float*)d_in[8];
    const float* bs  = (const float*)d_in[9];
    const float* Wr  = (const float*)d_in[10];
    const float* br  = (const float*)d_in[11];
    const float* wd  = (const float*)d_in[12];
    const float* bd  = (const float*)d_in[13];
    const float* fcW = (const float*)d_in[14];
    const float* fcb = (const float*)d_in[15];
    float* out = (float*)d_out;

    const int blkSmem = (6144 + 32*SH_STR + 32*SO_STR) * 4;   // 95232 B
    cudaFuncSetAttribute(wavenet_block<1,true>,   cudaFuncAttributeMaxDynamicSharedMemorySize, blkSmem);
    cudaFuncSetAttribute(wavenet_block<2,false>,  cudaFuncAttributeMaxDynamicSharedMemorySize, blkSmem);
    cudaFuncSetAttribute(wavenet_block<4,false>,  cudaFuncAttributeMaxDynamicSharedMemorySize, blkSmem);
    cudaFuncSetAttribute(wavenet_block<8,false>,  cudaFuncAttributeMaxDynamicSharedMemorySize, blkSmem);
    cudaFuncSetAttribute(wavenet_block<16,false>, cudaFuncAttributeMaxDynamicSharedMemorySize, blkSmem);
    cudaFuncSetAttribute(wavenet_block<32,false>, cudaFuncAttributeMaxDynamicSharedMemorySize, blkSmem);
    cudaFuncSetAttribute(downsample_kernel, cudaFuncAttributeMaxDynamicSharedMemorySize, 65536);
    cudaFuncSetAttribute(fc_kernel,         cudaFuncAttributeMaxDynamicSharedMemorySize, 8*FC_CHUNK*4);

    const int tiles = (Ll + TILE_T - 1) / TILE_T;   // 352
    conv0_kernel<<<dim3(tiles, Bb*Cc), 256>>>(x, w0, b0);

    dim3 bg2(tiles, Bb);
    // block i: weights offset i*2048 (Wf/Wg), i*1024 (Ws/Wr), i*32 (biases)
    wavenet_block<1,true  ><<<bg2, 256, blkSmem>>>(0, Wf+0*2048, bf+0*32, Wg+0*2048, bg+0*32, Ws+0*1024, bs+0*32, Wr+0*1024, br+0*32);
    wavenet_block<2,false ><<<bg2, 256, blkSmem>>>(1, Wf+1*2048, bf+1*32, Wg+1*2048, bg+1*32, Ws+1*1024, bs+1*32, Wr+1*1024, br+1*32);
    wavenet_block<4,false ><<<bg2, 256, blkSmem>>>(0, Wf+2*2048, bf+2*32, Wg+2*2048, bg+2*32, Ws+2*1024, bs+2*32, Wr+2*1024, br+2*32);
    wavenet_block<8,false ><<<bg2, 256, blkSmem>>>(1, Wf+3*2048, bf+3*32, Wg+3*2048, bg+3*32, Ws+3*1024, bs+3*32, Wr+3*1024, br+3*32);
    wavenet_block<16,false><<<bg2, 256, blkSmem>>>(0, Wf+4*2048, bf+4*32, Wg+4*2048, bg+4*32, Ws+4*1024, bs+4*32, Wr+4*1024, br+4*32);
    wavenet_block<32,false><<<bg2, 256, blkSmem>>>(1, Wf+5*2048, bf+5*32, Wg+5*2048, bg+5*32, Ws+5*1024, bs+5*32, Wr+5*1024, br+5*32);

    downsample_kernel<<<dim3((DOWNL + 63)/64, Bb), 256, 65536>>>(wd, bd);
    zero_o_kernel<<<1, 512>>>();
    fc_kernel<<<dim3(FLATN/FC_CHUNK, 2), 512, 8*FC_CHUNK*4>>>(fcW);
    final_kernel<<<1, 256>>>(eps, fcb, out);
}